// round 15
// baseline (speedup 1.0000x reference)
#include <cuda_runtime.h>

#define T_STEPS 50
#define BATCH   2048
#define D_IN    1156
#define H       128
#define OUT_N   10
#define KC      248          // Eigen kc (aarch64 default l1=16KB) -- verified exact

// Scratch: cur1[t][b][h] = (x[t,b,:] @ W1.T)[h]   (bias b1 added in scan)
__device__ float g_cur1[(size_t)T_STEPS * BATCH * H];  // 52.4 MB
// Per-timestep completion counters (16 GEMM tiles per timestep)
__device__ int g_cnt[T_STEPS];

__device__ __forceinline__ int ld_acquire_gpu(const int* p) {
    int v;
    asm volatile("ld.acquire.gpu.b32 %0, [%1];" : "=r"(v) : "l"(p) : "memory");
    return v;
}

// GEMM dynamic smem: 16KB used, padded to 120KB to force 1 block/SM so a
// scan block can co-reside (regs: 512*64 + 512*64 = 64K; smem 120K+70K<228K).
#define GEMM_SMEM_BYTES (120 * 1024)

// ---------------------------------------------------------------------------
// SGEMM emulating Eigen gebp (bit-exact, verified): KC=248 panels, each an
// ascending-k FMA chain per element, folded left-to-right in GMEM.
// 128x128 tile, BK=8, 512 threads, 8x4 micro-tile, double-buffered smem,
// 1 block/SM (smem-enforced) -- same 4 warps/SMSP as the proven 2x256 config,
// so still at the FFMA issue floor. Signals g_cnt[t] after the final fold.
// ---------------------------------------------------------------------------
__global__ __launch_bounds__(512, 2)   // reg cap 63/thread
void gemm_xw1(const float* __restrict__ A, const float* __restrict__ W, int M, int K) {
    const int BK = 8;
    extern __shared__ float sm[];
    float* As = sm;                    // [2][BK][128]
    float* Bs = sm + 2 * BK * 128;     // [2][BK][128]

    int tid = threadIdx.x;
    int block_m = blockIdx.x * 128;
    int tx = tid & 31;                 // 0..31 -> 4 cols each
    int ty = tid >> 5;                 // 0..15 -> 8 rows each (warp-uniform)

    float acc[8][4];
#pragma unroll
    for (int i = 0; i < 8; i++)
#pragma unroll
        for (int j = 0; j < 4; j++) acc[i][j] = 0.f;

    // Tile loaders: threads 0-255 load A, 256-511 load B (1 float4 each).
    int isB  = tid >> 8;
    int lRow = (tid & 255) >> 1;
    int lCol = (tid & 1) * 4;
    const float* src = isB ? (W + (size_t)lRow * K)
                           : (A + (size_t)(block_m + lRow) * K);
    float* dstb = isB ? Bs : As;

    const int NIT = (K + BK - 1) / BK;   // 145

    float4 v;
    {   // fetch tile 0
        v = make_float4(0.f, 0.f, 0.f, 0.f);
        if (lCol < K) v = *(const float4*)(src + lCol);
        dstb[(0 * BK + lCol + 0) * 128 + lRow] = v.x;
        dstb[(0 * BK + lCol + 1) * 128 + lRow] = v.y;
        dstb[(0 * BK + lCol + 2) * 128 + lRow] = v.z;
        dstb[(0 * BK + lCol + 3) * 128 + lRow] = v.w;
    }
    __syncthreads();

    int panel_done = 0;
    float* cbase = g_cur1 + (size_t)(block_m + ty * 8) * H + tx * 4;

    for (int it = 0; it < NIT; it++) {
        int cur = it & 1;
        int nxt = cur ^ 1;

        if (it + 1 < NIT) {   // prefetch next tile while computing current
            int k0 = (it + 1) * BK;
            v = make_float4(0.f, 0.f, 0.f, 0.f);
            if (k0 + lCol < K) v = *(const float4*)(src + k0 + lCol);  // zero-pad tail
        }

#pragma unroll
        for (int kk = 0; kk < BK; kk++) {
            const float* arow = As + (cur * BK + kk) * 128 + ty * 8;
            const float* brow = Bs + (cur * BK + kk) * 128 + tx * 4;
            float ra[8], rb[4];
            *(float4*)(ra)     = *(const float4*)(arow);      // warp-uniform bcast
            *(float4*)(ra + 4) = *(const float4*)(arow + 4);
            *(float4*)(rb)     = *(const float4*)(brow);
#pragma unroll
            for (int i = 0; i < 8; i++)
#pragma unroll
                for (int j = 0; j < 4; j++)
                    acc[i][j] = __fmaf_rn(ra[i], rb[j], acc[i][j]);
        }

        if (it + 1 < NIT) {
            dstb[(nxt * BK + lCol + 0) * 128 + lRow] = v.x;
            dstb[(nxt * BK + lCol + 1) * 128 + lRow] = v.y;
            dstb[(nxt * BK + lCol + 2) * 128 + lRow] = v.z;
            dstb[(nxt * BK + lCol + 3) * 128 + lRow] = v.w;
        }
        __syncthreads();

        // Eigen panel boundary: fold partial into C (gmem), left-to-right.
        int knext = (it + 1) * BK;
        if ((knext % KC) == 0 || knext >= K) {
            if (panel_done == 0) {
#pragma unroll
                for (int i = 0; i < 8; i++)
                    *(float4*)(cbase + (size_t)i * H) =
                        make_float4(acc[i][0], acc[i][1], acc[i][2], acc[i][3]);
            } else {
#pragma unroll
                for (int i = 0; i < 8; i++) {
                    float* crow = cbase + (size_t)i * H;
                    float4 c = *(float4*)(crow);
                    c.x = __fadd_rn(c.x, acc[i][0]);
                    c.y = __fadd_rn(c.y, acc[i][1]);
                    c.z = __fadd_rn(c.z, acc[i][2]);
                    c.w = __fadd_rn(c.w, acc[i][3]);
                    *(float4*)(crow) = c;
                }
            }
            panel_done++;
#pragma unroll
            for (int i = 0; i < 8; i++)
#pragma unroll
                for (int j = 0; j < 4; j++) acc[i][j] = 0.f;
        }
    }

    // Signal: this tile (128 M-rows, all within one timestep) is complete.
    __threadfence();
    __syncthreads();
    if (tid == 0) atomicAdd(&g_cnt[block_m >> 11], 1);   // 2048 rows per t
}

// ---------------------------------------------------------------------------
// Persistent sparse LIF scan (R10 version, verified 233.8us): 8 rows/block,
// 512 threads, two rows per thread, per-row-group named barriers,
// double-buffered masks/spk2, per-timestep acquire-poll on g_cnt[t].
// ---------------------------------------------------------------------------
#define ROWS_PB 8
#define SCAN_THREADS 512
#define V1T_STRIDE 129
#define V1T_ELEMS (128 * V1T_STRIDE)
#define W2_STRIDE 129
#define SCAN_SMEM_FLOATS (V1T_ELEMS + OUT_N * W2_STRIDE + 2*ROWS_PB*OUT_N + 2*ROWS_PB*4)
#define SCAN_SMEM_BYTES (SCAN_SMEM_FLOATS * 4)

__global__ __launch_bounds__(SCAN_THREADS, 2)
void scan_kernel(const float* __restrict__ b1, const float* __restrict__ V1,
                 const float* __restrict__ bV1, const float* __restrict__ W2,
                 const float* __restrict__ b2, const float* __restrict__ V2,
                 const float* __restrict__ bV2, float* __restrict__ out) {
    extern __shared__ float smem[];
    float* V1t   = smem;                                  // [j*129 + h] = V1[h][j]
    float* W2s   = smem + V1T_ELEMS;                      // [o*129 + j]
    float* sspk2 = W2s + OUT_N * W2_STRIDE;               // [buf][row][10]
    unsigned* s_mask = (unsigned*)(sspk2 + 2 * ROWS_PB * OUT_N); // [buf][row][4]

    int tid  = threadIdx.x;
    int h    = tid & 127;
    int q    = tid >> 7;             // row group 0..3; thread owns rows q and q+4
    int rA   = q;
    int rB   = q + 4;
    int bA   = blockIdx.x * ROWS_PB + rA;
    int bB   = blockIdx.x * ROWS_PB + rB;
    int wid  = tid >> 5;             // warp 0..15; group = wid>>2, word = wid&3
    int word = wid & 3;

    for (int idx = tid; idx < 128 * 128; idx += SCAN_THREADS) {
        int rr = idx >> 7, cc = idx & 127;
        V1t[cc * V1T_STRIDE + rr] = V1[idx];
    }
    for (int idx = tid; idx < OUT_N * 128; idx += SCAN_THREADS) {
        int o = idx >> 7, j = idx & 127;
        W2s[o * W2_STRIDE + j] = W2[idx];
    }
    if (tid < 2 * ROWS_PB * OUT_N) sspk2[tid] = 0.f;
    if (tid < 2 * ROWS_PB * 4) s_mask[tid] = 0u;

    float V2row[OUT_N];
    float b2h = 0.f, bV2h = 0.f, mem2A = 0.f, mem2B = 0.f;
    if (h < OUT_N) {
#pragma unroll
        for (int p = 0; p < OUT_N; p++) V2row[p] = V2[h * OUT_N + p];
        b2h = b2[h]; bV2h = bV2[h];
    }

    float b1h  = b1[h];
    float bV1h = bV1[h];
    float mem1A = 0.f, mem1B = 0.f;
    const float* curA = g_cur1 + (size_t)bA * H + h;
    const float* curB = g_cur1 + (size_t)bB * H + h;
    float* outA = out + (size_t)bA * OUT_N + h;
    float* outB = out + (size_t)bB * OUT_N + h;
    const float* colh = V1t + h;
    __syncthreads();                 // V1t/W2s/init visible to all

    for (int t = 0; t < T_STEPS; t++) {
        int pw = t & 1;
        int pr = pw ^ 1;

        // ---- layer 1 rec terms for both rows (independent chains) ----
        float recA = 0.f, recB = 0.f;
#pragma unroll
        for (int w = 0; w < 4; w++) {
            unsigned mA = s_mask[(pr * ROWS_PB + rA) * 4 + w];
            unsigned mB = s_mask[(pr * ROWS_PB + rB) * 4 + w];
            const float* base = colh + (w * 32) * V1T_STRIDE;
            while (mA) {
                int j = __ffs(mA) - 1; mA &= mA - 1;
                recA = __fadd_rn(recA, base[j * V1T_STRIDE]);
            }
            while (mB) {
                int j = __ffs(mB) - 1; mB &= mB - 1;
                recB = __fadd_rn(recB, base[j * V1T_STRIDE]);
            }
        }

        // GEMM data for timestep t needed from here on.
        while (ld_acquire_gpu(&g_cnt[t]) < 16) __nanosleep(200);

        float gvA = curA[(size_t)t * BATCH * H];
        float gvB = curB[(size_t)t * BATCH * H];

        float aA = __fmul_rn(0.9f, mem1A);
        aA = __fadd_rn(aA, __fadd_rn(gvA, b1h));
        aA = __fadd_rn(aA, recA);
        aA = __fadd_rn(aA, bV1h);
        float resetA = (mem1A > 1.0f) ? 1.0f : 0.0f;
        mem1A = __fsub_rn(aA, resetA);
        float spkA = (mem1A > 1.0f) ? 1.0f : 0.0f;

        float aB = __fmul_rn(0.9f, mem1B);
        aB = __fadd_rn(aB, __fadd_rn(gvB, b1h));
        aB = __fadd_rn(aB, recB);
        aB = __fadd_rn(aB, bV1h);
        float resetB = (mem1B > 1.0f) ? 1.0f : 0.0f;
        mem1B = __fsub_rn(aB, resetB);
        float spkB = (mem1B > 1.0f) ? 1.0f : 0.0f;

        unsigned balA = __ballot_sync(0xffffffffu, spkA != 0.0f);
        unsigned balB = __ballot_sync(0xffffffffu, spkB != 0.0f);
        if ((tid & 31) == 0) {
            s_mask[(pw * ROWS_PB + rA) * 4 + word] = balA;
            s_mask[(pw * ROWS_PB + rB) * 4 + word] = balB;
        }
        // per-row-group barrier: syncs the 4 warps (128 threads) of group q
        asm volatile("bar.sync %0, 128;" :: "r"(1 + q) : "memory");

        // ---- layer 2 for both rows (lanes h<10 of first warp of group) ----
        if (h < OUT_N) {
            const float* w2 = W2s + h * W2_STRIDE;
            float c2A = 0.f, c2B = 0.f;
#pragma unroll
            for (int w = 0; w < 4; w++) {
                unsigned nA = s_mask[(pw * ROWS_PB + rA) * 4 + w];
                unsigned nB = s_mask[(pw * ROWS_PB + rB) * 4 + w];
                const float* base = w2 + w * 32;
                while (nA) {
                    int j = __ffs(nA) - 1; nA &= nA - 1;
                    c2A = __fadd_rn(c2A, base[j]);
                }
                while (nB) {
                    int j = __ffs(nB) - 1; nB &= nB - 1;
                    c2B = __fadd_rn(c2B, base[j]);
                }
            }
            float rec2A = 0.f, rec2B = 0.f;
            const float* spA = sspk2 + (pr * ROWS_PB + rA) * OUT_N;
            const float* spB = sspk2 + (pr * ROWS_PB + rB) * OUT_N;
#pragma unroll
            for (int p = 0; p < OUT_N; p++) {
                if (spA[p] != 0.0f) rec2A = __fadd_rn(rec2A, V2row[p]);
                if (spB[p] != 0.0f) rec2B = __fadd_rn(rec2B, V2row[p]);
            }
            float uA = __fmul_rn(0.9f, mem2A);
            uA = __fadd_rn(uA, __fadd_rn(c2A, b2h));
            uA = __fadd_rn(uA, rec2A);
            uA = __fadd_rn(uA, bV2h);
            float reset2A = (mem2A > 1.0f) ? 1.0f : 0.0f;
            mem2A = __fsub_rn(uA, reset2A);
            float s2A = (mem2A > 1.0f) ? 1.0f : 0.0f;

            float uB = __fmul_rn(0.9f, mem2B);
            uB = __fadd_rn(uB, __fadd_rn(c2B, b2h));
            uB = __fadd_rn(uB, rec2B);
            uB = __fadd_rn(uB, bV2h);
            float reset2B = (mem2B > 1.0f) ? 1.0f : 0.0f;
            mem2B = __fsub_rn(uB, reset2B);
            float s2B = (mem2B > 1.0f) ? 1.0f : 0.0f;

            outA[(size_t)t * BATCH * OUT_N] = s2A;
            outB[(size_t)t * BATCH * OUT_N] = s2B;
            sspk2[(pw * ROWS_PB + rA) * OUT_N + h] = s2A;
            sspk2[(pw * ROWS_PB + rB) * OUT_N + h] = s2B;
        }
        // next step's group barrier orders these writes vs reads at t+1
    }
}

extern "C" void kernel_launch(void* const* d_in, const int* in_sizes, int n_in,
                              void* d_out, int out_size) {
    const float* x   = (const float*)d_in[0];
    const float* W1  = (const float*)d_in[1];
    const float* b1  = (const float*)d_in[2];
    const float* V1  = (const float*)d_in[3];
    const float* bV1 = (const float*)d_in[4];
    const float* W2  = (const float*)d_in[5];
    const float* b2  = (const float*)d_in[6];
    const float* V2  = (const float*)d_in[7];
    const float* bV2 = (const float*)d_in[8];
    float* out = (float*)d_out;

    cudaFuncSetAttribute(gemm_xw1, cudaFuncAttributeMaxDynamicSharedMemorySize,
                         GEMM_SMEM_BYTES);
    cudaFuncSetAttribute(scan_kernel, cudaFuncAttributeMaxDynamicSharedMemorySize,
                         SCAN_SMEM_BYTES);

    // Zero the per-timestep completion counters (captured async memset).
    void* cnt_addr = nullptr;
    cudaGetSymbolAddress(&cnt_addr, g_cnt);
    cudaMemsetAsync(cnt_addr, 0, T_STEPS * sizeof(int), 0);

    // Fork a side stream for the scan so it can run co-resident with the GEMM.
    cudaStream_t s2;
    cudaStreamCreateWithFlags(&s2, cudaStreamNonBlocking);
    cudaEvent_t eF, eJ;
    cudaEventCreateWithFlags(&eF, cudaEventDisableTiming);
    cudaEventCreateWithFlags(&eJ, cudaEventDisableTiming);

    cudaEventRecord(eF, 0);           // after memset on the capture stream
    cudaStreamWaitEvent(s2, eF, 0);

    const int M = T_STEPS * BATCH;    // 102400
    // GEMM launched FIRST (FIFO dispatch -> scan can never starve it).
    // 1 block/SM (smem-enforced) leaves room for one scan block per SM.
    gemm_xw1<<<M / 128, 512, GEMM_SMEM_BYTES, 0>>>(x, W1, M, D_IN);
    scan_kernel<<<BATCH / ROWS_PB, SCAN_THREADS, SCAN_SMEM_BYTES, s2>>>(
        b1, V1, bV1, W2, b2, V2, bV2, out);

    cudaEventRecord(eJ, s2);          // join scan back into the capture stream
    cudaStreamWaitEvent(0, eJ, 0);

    cudaEventDestroy(eF);
    cudaEventDestroy(eJ);
    cudaStreamDestroy(s2);
}